// round 1
// baseline (speedup 1.0000x reference)
#include <cuda_runtime.h>

// ConvCNP: B=4, N=2048, M=8192, CIN=1, C=2, COUT=64
// out[b,m,:] = [density, conv] @ W.T + bias
//   density = sum_n exp(-0.5*(x_n - t_m)^2 / s0^2)
//   num     = sum_n ctx_out_n * exp(-0.5*(x_n - t_m)^2 / s1^2)
//   conv    = num / (density + 1e-8)
// with s_c = exp(sigma_c).

#define BATCH 4
#define NCTX  2048
#define MTGT  8192
#define NOUT  64
#define BLOCK 128

__device__ __forceinline__ float ex2f(float x) {
    float y;
    asm("ex2.approx.f32 %0, %1;" : "=f"(y) : "f"(x));
    return y;
}

__global__ __launch_bounds__(BLOCK) void convcnp_kernel(
    const float* __restrict__ context_in,    // [B, N]
    const float* __restrict__ context_out,   // [B, N]
    const float* __restrict__ target_in,     // [B, M]
    const float* __restrict__ sigma,         // [2]
    const float* __restrict__ W,             // [64, 2] row-major
    const float* __restrict__ bias,          // [64]
    float* __restrict__ out)                 // [B, M, 64]
{
    __shared__ float2 s_ctx[NCTX];          // (x_n, ctx_out_n)
    __shared__ float2 s_res[BLOCK];         // (density, conv) per target
    __shared__ float  s_W0[NOUT], s_W1[NOUT], s_b[NOUT];

    const int tile = blockIdx.x;                       // 0..255
    const int b    = tile / (MTGT / BLOCK);            // batch
    const int m0   = (tile % (MTGT / BLOCK)) * BLOCK;  // first target of tile
    const int tid  = threadIdx.x;

    // Stage context for this batch into shared memory.
    const float* __restrict__ xin = context_in  + b * NCTX;
    const float* __restrict__ cov = context_out + b * NCTX;
    #pragma unroll
    for (int i = tid; i < NCTX; i += BLOCK)
        s_ctx[i] = make_float2(xin[i], cov[i]);

    if (tid < NOUT) {
        s_W0[tid] = W[tid * 2 + 0];
        s_W1[tid] = W[tid * 2 + 1];
        s_b[tid]  = bias[tid];
    }
    __syncthreads();

    // Fold log2(e) so each weight is a single ex2.approx:
    //   exp(-0.5*d/s_c^2) = 2^(d * k_c),  k_c = -0.5*log2(e)*exp(-2*sigma_c)
    const float LOG2E = 1.4426950408889634f;
    const float k0 = -0.5f * LOG2E * __expf(-2.0f * sigma[0]);
    const float k1 = -0.5f * LOG2E * __expf(-2.0f * sigma[1]);

    const float t = target_in[b * MTGT + m0 + tid];

    float acc0 = 0.0f, acc1 = 0.0f;
    #pragma unroll 8
    for (int n = 0; n < NCTX; n++) {
        float2 cw = s_ctx[n];
        float  d  = cw.x - t;
        float  s  = d * d;
        acc0 += ex2f(s * k0);
        acc1 = fmaf(cw.y, ex2f(s * k1), acc1);
    }

    const float conv = acc1 / (acc0 + 1e-8f);
    s_res[tid] = make_float2(acc0, conv);
    __syncthreads();

    // Coalesced epilogue: 128 targets x 64 outputs.
    float* __restrict__ outp = out + ((long)b * MTGT + m0) * NOUT;
    #pragma unroll
    for (int idx = tid; idx < BLOCK * NOUT; idx += BLOCK) {
        const int mi = idx >> 6;      // target within tile
        const int j  = idx & 63;      // output channel
        const float2 r = s_res[mi];
        outp[(long)mi * NOUT + j] = fmaf(r.x, s_W0[j], fmaf(r.y, s_W1[j], s_b[j]));
    }
}

extern "C" void kernel_launch(void* const* d_in, const int* in_sizes, int n_in,
                              void* d_out, int out_size) {
    const float* context_in  = (const float*)d_in[0];
    const float* context_out = (const float*)d_in[1];
    const float* target_in   = (const float*)d_in[2];
    const float* sigma       = (const float*)d_in[3];
    const float* W           = (const float*)d_in[4];
    const float* bias        = (const float*)d_in[5];
    float* out = (float*)d_out;

    const int nblocks = (BATCH * MTGT) / BLOCK;   // 256
    convcnp_kernel<<<nblocks, BLOCK>>>(context_in, context_out, target_in,
                                       sigma, W, bias, out);
}

// round 2
// speedup vs baseline: 1.6384x; 1.6384x over previous
#include <cuda_runtime.h>

// ConvCNP: B=4, N=2048, M=8192, CIN=1, C=2, COUT=64
// density = sum_n exp(-0.5*(x_n - t_m)^2 / s0^2)
// num     = sum_n w_n * exp(-0.5*(x_n - t_m)^2 / s1^2)
// out[b,m,:] = [density, num/(density+eps)] @ W.T + bias,  s_c = exp(sigma_c)

#define BATCH  4
#define NCTX   2048
#define MTGT   8192
#define NOUT   64
#define TTILE  32              // targets per block
#define BLOCK  128             // 4 warps
#define NSPLIT 4               // warps split the context dim
#define CHUNK2 (NCTX / NSPLIT / 2)   // 256 packed (x2) iterations per warp

typedef unsigned long long u64;

__device__ __forceinline__ float ex2f(float x) {
    float y; asm("ex2.approx.f32 %0, %1;" : "=f"(y) : "f"(x)); return y;
}
__device__ __forceinline__ u64 pack2(float lo, float hi) {
    u64 r; asm("mov.b64 %0, {%1, %2};" : "=l"(r) : "f"(lo), "f"(hi)); return r;
}
__device__ __forceinline__ void unpack2(u64 v, float& lo, float& hi) {
    asm("mov.b64 {%0, %1}, %2;" : "=f"(lo), "=f"(hi) : "l"(v));
}
__device__ __forceinline__ u64 add2(u64 a, u64 b) {
    u64 r; asm("add.rn.f32x2 %0, %1, %2;" : "=l"(r) : "l"(a), "l"(b)); return r;
}
__device__ __forceinline__ u64 mul2(u64 a, u64 b) {
    u64 r; asm("mul.rn.f32x2 %0, %1, %2;" : "=l"(r) : "l"(a), "l"(b)); return r;
}
__device__ __forceinline__ u64 fma2(u64 a, u64 b, u64 c) {
    u64 r; asm("fma.rn.f32x2 %0, %1, %2, %3;" : "=l"(r) : "l"(a), "l"(b), "l"(c)); return r;
}

__global__ __launch_bounds__(BLOCK) void convcnp_kernel(
    const float* __restrict__ context_in,    // [B, N]
    const float* __restrict__ context_out,   // [B, N]
    const float* __restrict__ target_in,     // [B, M]
    const float* __restrict__ sigma,         // [2]
    const float* __restrict__ W,             // [64, 2]
    const float* __restrict__ bias,          // [64]
    float* __restrict__ out)                 // [B, M, 64]
{
    __shared__ float2 s_x2[NCTX / 2];        // packed context positions
    __shared__ float2 s_w2[NCTX / 2];        // packed context values
    __shared__ float  s_pd[NSPLIT][TTILE];   // per-warp partial density
    __shared__ float  s_pn[NSPLIT][TTILE];   // per-warp partial numerator
    __shared__ float2 s_res[TTILE];          // (density, conv)

    const int tile = blockIdx.x;                        // 0..1023
    const int b    = tile / (MTGT / TTILE);
    const int m0   = (tile % (MTGT / TTILE)) * TTILE;
    const int tid  = threadIdx.x;
    const int w    = tid >> 5;
    const int lane = tid & 31;

    // Stage this batch's context into shared memory (float4 copies).
    {
        const float4* __restrict__ xin4 = (const float4*)(context_in  + b * NCTX);
        const float4* __restrict__ cov4 = (const float4*)(context_out + b * NCTX);
        float4* sx4 = (float4*)s_x2;
        float4* sw4 = (float4*)s_w2;
        #pragma unroll
        for (int i = tid; i < NCTX / 4; i += BLOCK) {
            sx4[i] = xin4[i];
            sw4[i] = cov4[i];
        }
    }
    __syncthreads();

    // exp(-0.5*d/s_c^2) = 2^(d*k_c),  k_c = -0.5*log2(e)*exp(-2*sigma_c)
    const float LOG2E = 1.4426950408889634f;
    const float k0 = -0.5f * LOG2E * __expf(-2.0f * sigma[0]);
    const float k1 = -0.5f * LOG2E * __expf(-2.0f * sigma[1]);

    const float t  = target_in[b * MTGT + m0 + lane];
    const u64 nt2  = pack2(-t, -t);

    const float2* __restrict__ px = s_x2 + w * CHUNK2;
    const float2* __restrict__ pw = s_w2 + w * CHUNK2;

    u64 acc0 = pack2(0.0f, 0.0f);
    u64 acc1 = acc0;

    if (k0 == k1) {
        // Equal scales: the two Gaussian weights are identical -> 1 EX2 per pair.
        const u64 kk = pack2(k0, k0);
        #pragma unroll 8
        for (int i = 0; i < CHUNK2; i++) {
            float2 xv = px[i];
            float2 wv = pw[i];
            u64 x2  = pack2(xv.x, xv.y);
            u64 w2v = pack2(wv.x, wv.y);
            u64 d = add2(x2, nt2);
            u64 s = mul2(d, d);
            u64 a = mul2(s, kk);
            float al, ah; unpack2(a, al, ah);
            u64 e = pack2(ex2f(al), ex2f(ah));
            acc0 = add2(acc0, e);
            acc1 = fma2(w2v, e, acc1);
        }
    } else {
        // Generic path: distinct scales, 2 EX2 per pair.
        const u64 kk0 = pack2(k0, k0);
        const u64 kk1 = pack2(k1, k1);
        #pragma unroll 8
        for (int i = 0; i < CHUNK2; i++) {
            float2 xv = px[i];
            float2 wv = pw[i];
            u64 x2  = pack2(xv.x, xv.y);
            u64 w2v = pack2(wv.x, wv.y);
            u64 d = add2(x2, nt2);
            u64 s = mul2(d, d);
            u64 a0 = mul2(s, kk0);
            u64 a1 = mul2(s, kk1);
            float a0l, a0h, a1l, a1h;
            unpack2(a0, a0l, a0h);
            unpack2(a1, a1l, a1h);
            u64 e0 = pack2(ex2f(a0l), ex2f(a0h));
            u64 e1 = pack2(ex2f(a1l), ex2f(a1h));
            acc0 = add2(acc0, e0);
            acc1 = fma2(w2v, e1, acc1);
        }
    }

    // Fold packed halves; publish per-warp partials.
    float d0, d1, n0, n1;
    unpack2(acc0, d0, d1);
    unpack2(acc1, n0, n1);
    s_pd[w][lane] = d0 + d1;
    s_pn[w][lane] = n0 + n1;
    __syncthreads();

    if (tid < TTILE) {
        float den = s_pd[0][tid] + s_pd[1][tid] + s_pd[2][tid] + s_pd[3][tid];
        float num = s_pn[0][tid] + s_pn[1][tid] + s_pn[2][tid] + s_pn[3][tid];
        s_res[tid] = make_float2(den, num / (den + 1e-8f));
    }
    __syncthreads();

    // Epilogue: 32 targets x 64 channels = 512 float4 stores, coalesced.
    float4* __restrict__ outp = (float4*)(out + ((long)b * MTGT + m0) * NOUT);
    const int j0 = (tid & 15) * 4;          // channel group handled by this thread
    float W0[4], W1[4], bb[4];
    #pragma unroll
    for (int q = 0; q < 4; q++) {
        W0[q] = W[(j0 + q) * 2 + 0];
        W1[q] = W[(j0 + q) * 2 + 1];
        bb[q] = bias[j0 + q];
    }
    #pragma unroll
    for (int k = 0; k < 4; k++) {
        const int idx4 = tid + k * BLOCK;   // 0..511
        const int mi   = idx4 >> 4;         // target within tile
        const float2 r = s_res[mi];
        float4 v;
        v.x = fmaf(r.x, W0[0], fmaf(r.y, W1[0], bb[0]));
        v.y = fmaf(r.x, W0[1], fmaf(r.y, W1[1], bb[1]));
        v.z = fmaf(r.x, W0[2], fmaf(r.y, W1[2], bb[2]));
        v.w = fmaf(r.x, W0[3], fmaf(r.y, W1[3], bb[3]));
        outp[idx4] = v;
    }
}

extern "C" void kernel_launch(void* const* d_in, const int* in_sizes, int n_in,
                              void* d_out, int out_size) {
    const float* context_in  = (const float*)d_in[0];
    const float* context_out = (const float*)d_in[1];
    const float* target_in   = (const float*)d_in[2];
    const float* sigma       = (const float*)d_in[3];
    const float* W           = (const float*)d_in[4];
    const float* bias        = (const float*)d_in[5];
    float* out = (float*)d_out;

    const int nblocks = (BATCH * MTGT) / TTILE;   // 1024
    convcnp_kernel<<<nblocks, BLOCK>>>(context_in, context_out, target_in,
                                       sigma, W, bias, out);
}

// round 3
// speedup vs baseline: 3.1765x; 1.9387x over previous
#include <cuda_runtime.h>

// ConvCNP via 1-D Fast Gauss Transform (Hermite expansion).
//   density(t) = sum_n exp(-(u_n-t)^2/d0),  d_c = 2*exp(2*sigma_c)
//   num(t)     = sum_n w_n exp(-(u_n-t)^2/d1)
//   out[b,m,:] = [density, num/(density+1e-8)] @ W.T + bias
//
// e^{-(x-z)^2} = sum_k h_k(x) z^k / k!,  h_k = e^{-x^2} H_k(x),
// h_{k+1} = 2x h_k - 2k h_{k-1}.  Targets use boxes of width sqrt(delta_min)
// so |z| <= 0.5; truncation at P=20 is ~1e-12 per pair.

#define BATCH  4
#define NCTX   2048
#define MTGT   8192
#define NOUT   64
#define P      20
#define MAXBOX 64
#define SSPLIT 3
#define BLOCK1 256
#define BLOCK2 128
#define XMIN   (-8.0f)
#define XRANGE 16.0f
#define SQRT2  1.41421356237f
#define LOG2E  1.44269504089f

__device__ float g_part[SSPLIT][BATCH][MAXBOX][2][P];

__constant__ float c_invfact[P] = {
    1.0f, 1.0f, 0.5f, 1.6666667e-1f, 4.1666667e-2f,
    8.3333333e-3f, 1.3888889e-3f, 1.9841270e-4f, 2.4801587e-5f, 2.7557319e-6f,
    2.7557319e-7f, 2.5052108e-8f, 2.0876757e-9f, 1.6059044e-10f, 1.1470746e-11f,
    7.6471637e-13f, 4.7794773e-14f, 2.8114573e-15f, 1.5619206e-16f, 8.2206352e-18f
};

__device__ __forceinline__ float ex2f(float x) {
    float y; asm("ex2.approx.f32 %0, %1;" : "=f"(y) : "f"(x)); return y;
}

// ---------------- Pass 1: Hermite coefficients per (batch, box) ----------------
__global__ __launch_bounds__(BLOCK1) void fgt_coef_kernel(
    const float* __restrict__ context_in,    // [B, N]
    const float* __restrict__ context_out,   // [B, N]
    const float* __restrict__ sigma)         // [2]
{
    const int bid = blockIdx.x;              // B * MAXBOX * SSPLIT
    const int ss  = bid % SSPLIT;
    const int box = (bid / SSPLIT) % MAXBOX;
    const int b   = bid / (SSPLIT * MAXBOX);

    const float s0 = __expf(sigma[0]), s1 = __expf(sigma[1]);
    const float sd0 = s0 * SQRT2, sd1 = s1 * SQRT2;    // sqrt(delta_c)
    const float wbox = fminf(sd0, sd1);
    const int nbox = (int)ceilf(XRANGE / wbox);
    if (nbox > MAXBOX) return;               // brute-force fallback handles it
    if (box >= nbox) return;

    const float cbox = XMIN + (box + 0.5f) * wbox;
    const float isd0 = 1.0f / sd0, isd1 = 1.0f / sd1;

    float a0[P], a1[P];
    #pragma unroll
    for (int k = 0; k < P; k++) { a0[k] = 0.0f; a1[k] = 0.0f; }

    const int nlo = (NCTX * ss) / SSPLIT;
    const int nhi = (NCTX * (ss + 1)) / SSPLIT;
    const float* __restrict__ uin = context_in  + b * NCTX;
    const float* __restrict__ win = context_out + b * NCTX;

    if (sd0 == sd1) {
        // Equal scales: one recurrence feeds both channels.
        for (int n = nlo + threadIdx.x; n < nhi; n += BLOCK1) {
            const float u = uin[n], w = win[n];
            const float t  = (u - cbox) * isd0;
            const float h0 = ex2f(-t * t * LOG2E);
            const float t2 = t + t;
            float hm = h0, hc = t2 * h0;
            a0[0] += h0;                 a1[0] = fmaf(w, h0, a1[0]);
            a0[1] += hc;                 a1[1] = fmaf(w, hc, a1[1]);
            #pragma unroll
            for (int k = 1; k < P - 1; k++) {
                const float m  = (2.0f * k) * hm;
                const float hn = fmaf(t2, hc, -m);
                a0[k + 1] += hn;         a1[k + 1] = fmaf(w, hn, a1[k + 1]);
                hm = hc; hc = hn;
            }
        }
    } else {
        for (int n = nlo + threadIdx.x; n < nhi; n += BLOCK1) {
            const float u = uin[n], w = win[n];
            {   // channel 0 (density, weight 1)
                const float t  = (u - cbox) * isd0;
                const float h0 = ex2f(-t * t * LOG2E);
                const float t2 = t + t;
                float hm = h0, hc = t2 * h0;
                a0[0] += h0; a0[1] += hc;
                #pragma unroll
                for (int k = 1; k < P - 1; k++) {
                    const float m  = (2.0f * k) * hm;
                    const float hn = fmaf(t2, hc, -m);
                    a0[k + 1] += hn; hm = hc; hc = hn;
                }
            }
            {   // channel 1 (numerator, weight w)
                const float t  = (u - cbox) * isd1;
                const float h0 = ex2f(-t * t * LOG2E);
                const float t2 = t + t;
                float hm = h0, hc = t2 * h0;
                a1[0] = fmaf(w, h0, a1[0]); a1[1] = fmaf(w, hc, a1[1]);
                #pragma unroll
                for (int k = 1; k < P - 1; k++) {
                    const float m  = (2.0f * k) * hm;
                    const float hn = fmaf(t2, hc, -m);
                    a1[k + 1] = fmaf(w, hn, a1[k + 1]); hm = hc; hc = hn;
                }
            }
        }
    }

    // Block reduction: warp shuffles, then 2*P threads fold the 8 warps.
    __shared__ float s_red[BLOCK1 / 32][2 * P];
    #pragma unroll
    for (int k = 0; k < P; k++) {
        #pragma unroll
        for (int off = 16; off > 0; off >>= 1) {
            a0[k] += __shfl_down_sync(0xffffffffu, a0[k], off);
            a1[k] += __shfl_down_sync(0xffffffffu, a1[k], off);
        }
    }
    const int wrp = threadIdx.x >> 5, lane = threadIdx.x & 31;
    if (lane == 0) {
        #pragma unroll
        for (int k = 0; k < P; k++) {
            s_red[wrp][k]     = a0[k];
            s_red[wrp][P + k] = a1[k];
        }
    }
    __syncthreads();
    if (threadIdx.x < 2 * P) {
        float v = 0.0f;
        #pragma unroll
        for (int ww = 0; ww < BLOCK1 / 32; ww++) v += s_red[ww][threadIdx.x];
        const int ch = threadIdx.x / P, k = threadIdx.x % P;
        g_part[ss][b][box][ch][k] = v;
    }
}

// ---------------- Pass 2: per-target Horner eval + linear epilogue ----------------
__global__ __launch_bounds__(BLOCK2) void fgt_eval_kernel(
    const float* __restrict__ context_in,
    const float* __restrict__ context_out,
    const float* __restrict__ target_in,     // [B, M]
    const float* __restrict__ sigma,
    const float* __restrict__ W,             // [64, 2]
    const float* __restrict__ bias,          // [64]
    float* __restrict__ out)                 // [B, M, 64]
{
    __shared__ float  s_coef[P][2][MAXBOX];  // [k][ch][box] -> conflict-free LDS
    __shared__ float2 s_res[BLOCK2];

    const int tile = blockIdx.x;                         // 0..255
    const int b    = tile / (MTGT / BLOCK2);
    const int m0   = (tile % (MTGT / BLOCK2)) * BLOCK2;
    const int tid  = threadIdx.x;

    const float s0 = __expf(sigma[0]), s1 = __expf(sigma[1]);
    const float sd0 = s0 * SQRT2, sd1 = s1 * SQRT2;
    const float wbox = fminf(sd0, sd1);
    const int nbox = (int)ceilf(XRANGE / wbox);

    const float t = target_in[b * MTGT + m0 + tid];
    float den, num;

    if (nbox <= MAXBOX) {
        // Stage summed coefficients (folding 1/k!) into smem.
        const int tot = P * 2 * nbox;
        for (int idx = tid; idx < tot; idx += BLOCK2) {
            const int box = idx % nbox;
            const int r   = idx / nbox;
            const int ch  = r & 1;
            const int k   = r >> 1;
            float v = 0.0f;
            #pragma unroll
            for (int ssp = 0; ssp < SSPLIT; ssp++) v += g_part[ssp][b][box][ch][k];
            s_coef[k][ch][box] = v * c_invfact[k];
        }
        __syncthreads();

        int bi = (int)floorf((t - XMIN) / wbox);
        bi = max(0, min(nbox - 1, bi));
        const float cb = XMIN + (bi + 0.5f) * wbox;
        const float z0 = (t - cb) / sd0;
        const float z1 = (t - cb) / sd1;
        den = s_coef[P - 1][0][bi];
        num = s_coef[P - 1][1][bi];
        #pragma unroll
        for (int k = P - 2; k >= 0; k--) {
            den = fmaf(den, z0, s_coef[k][0][bi]);
            num = fmaf(num, z1, s_coef[k][1][bi]);
        }
    } else {
        // Brute-force fallback (exotic sigma; uniform branch across block).
        const float k0c = -0.5f * LOG2E / (s0 * s0);
        const float k1c = -0.5f * LOG2E / (s1 * s1);
        den = 0.0f; num = 0.0f;
        const float* __restrict__ uin = context_in  + b * NCTX;
        const float* __restrict__ win = context_out + b * NCTX;
        for (int n = 0; n < NCTX; n++) {
            const float u = __ldg(&uin[n]), w = __ldg(&win[n]);
            const float d = u - t, s = d * d;
            den += ex2f(s * k0c);
            num = fmaf(w, ex2f(s * k1c), num);
        }
    }

    const float conv = num / (den + 1e-8f);
    s_res[tid] = make_float2(den, conv);
    __syncthreads();

    // Epilogue: 128 targets x 64 channels = 2048 float4 stores, coalesced.
    float4* __restrict__ outp = (float4*)(out + ((long)b * MTGT + m0) * NOUT);
    const int j0 = (tid & 15) * 4;
    float W0[4], W1[4], bb[4];
    #pragma unroll
    for (int q = 0; q < 4; q++) {
        W0[q] = W[(j0 + q) * 2 + 0];
        W1[q] = W[(j0 + q) * 2 + 1];
        bb[q] = bias[j0 + q];
    }
    #pragma unroll
    for (int k = 0; k < 16; k++) {
        const int idx4 = tid + k * BLOCK2;   // 0..2047
        const int mi   = idx4 >> 4;
        const float2 r = s_res[mi];
        float4 v;
        v.x = fmaf(r.x, W0[0], fmaf(r.y, W1[0], bb[0]));
        v.y = fmaf(r.x, W0[1], fmaf(r.y, W1[1], bb[1]));
        v.z = fmaf(r.x, W0[2], fmaf(r.y, W1[2], bb[2]));
        v.w = fmaf(r.x, W0[3], fmaf(r.y, W1[3], bb[3]));
        outp[idx4] = v;
    }
}

extern "C" void kernel_launch(void* const* d_in, const int* in_sizes, int n_in,
                              void* d_out, int out_size) {
    const float* context_in  = (const float*)d_in[0];
    const float* context_out = (const float*)d_in[1];
    const float* target_in   = (const float*)d_in[2];
    const float* sigma       = (const float*)d_in[3];
    const float* W           = (const float*)d_in[4];
    const float* bias        = (const float*)d_in[5];
    float* out = (float*)d_out;

    fgt_coef_kernel<<<BATCH * MAXBOX * SSPLIT, BLOCK1>>>(context_in, context_out, sigma);
    fgt_eval_kernel<<<(BATCH * MTGT) / BLOCK2, BLOCK2>>>(context_in, context_out,
                                                         target_in, sigma, W, bias, out);
}